// round 13
// baseline (speedup 1.0000x reference)
#include <cuda_runtime.h>
#include <cuda_fp16.h>
#include <cstdint>

// ---------------- problem constants ----------------
#define B_ROWS 16384
#define DIN 512
#define DOUT 512
#define NE 8
#define GCOLS 2

// ---------------- GEMM tiling ----------------
#define TM 128
#define TN 128
#define TK 64
#define NSTAGE (DIN / TK)          // 8
#define NCOLT (DOUT / TN)          // 4

#define SA32 288   // A32 smem row stride BYTES (72 floats): 8g+2t bank pattern, conflict-free
#define SB 136     // B smem row stride (halves): 272B

// smem layout (bytes)
#define A32OF 1024
#define A32BUF (TM * SA32)              // 36864, double-buffered
#define B16OF (A32OF + 2 * A32BUF)      // 74752
#define B16BUF (TK * SB * 2)            // 17408, double-buffered
#define GEMM_SMEM (B16OF + 2 * B16BUF)  // 109568 -> 2 CTAs/SM (219KB <= 228KB)

#define GEMM_GRID 304   // 2 CTAs/SM x 152 SMs, all co-resident

// ---------------- device scratch ----------------
__device__ int g_fill[NE];       // zero at start; self-reset by gemm
__device__ int g_work;
__device__ int g_done;
__device__ int g_rowpad[NE * B_ROWS];

__device__ __align__(16) __half g_wh[NE * DIN * DOUT];   // 4MB, [e][k][n]

// ---------------- helpers ----------------
__device__ __forceinline__ uint32_t smem_u32(const void* p) {
    uint32_t a;
    asm("{ .reg .u64 t; cvta.to.shared.u64 t, %1; cvt.u32.u64 %0, t; }" : "=r"(a) : "l"(p));
    return a;
}
__device__ __forceinline__ void ldsm_x4_t(uint32_t* r, uint32_t addr) {
    asm volatile("ldmatrix.sync.aligned.m8n8.x4.trans.shared.b16 {%0,%1,%2,%3}, [%4];"
                 : "=r"(r[0]), "=r"(r[1]), "=r"(r[2]), "=r"(r[3]) : "r"(addr));
}
// load 2 consecutive fp32 from smem, convert to packed fp16x2 (lo = first)
__device__ __forceinline__ uint32_t lds_cvt(uint32_t addr) {
    float lo, hi; uint32_t r;
    asm volatile("ld.shared.v2.f32 {%0,%1}, [%2];" : "=f"(lo), "=f"(hi) : "r"(addr));
    asm volatile("cvt.rn.f16x2.f32 %0, %1, %2;" : "=r"(r) : "f"(hi), "f"(lo));
    return r;
}
__device__ __forceinline__ void mma_f16(float* c, const uint32_t* a, const uint32_t* b) {
    asm volatile(
        "mma.sync.aligned.m16n8k16.row.col.f32.f16.f16.f32 "
        "{%0,%1,%2,%3}, {%4,%5,%6,%7}, {%8,%9}, {%0,%1,%2,%3};"
        : "+f"(c[0]), "+f"(c[1]), "+f"(c[2]), "+f"(c[3])
        : "r"(a[0]), "r"(a[1]), "r"(a[2]), "r"(a[3]), "r"(b[0]), "r"(b[1]));
}
#define CP_ASYNC16(saddr, gaddr) \
    asm volatile("cp.async.cg.shared.global [%0], [%1], 16;" :: "r"(saddr), "l"(gaddr))
#define CP_COMMIT() asm volatile("cp.async.commit_group;")
#define CP_WAIT0()  asm volatile("cp.async.wait_group 0;" ::: "memory")

// ---------------- prep: cvt W, scatter ----------------
#define WBLOCKS (NE * DIN * DOUT / 4 / 256)    // 2048
#define SBLOCKS (B_ROWS / 256)                 // 64
#define PREP_GRID (WBLOCKS + SBLOCKS)

__global__ void prep_kernel(const float* __restrict__ W, const int* __restrict__ groups) {
    int bid = blockIdx.x;
    if (bid < WBLOCKS) {
        int i = bid * blockDim.x + threadIdx.x;
        float4 v = ((const float4*)W)[i];
        __half2 h0 = __floats2half2_rn(v.x, v.y);
        __half2 h1 = __floats2half2_rn(v.z, v.w);
        ((uint2*)g_wh)[i] = make_uint2(*(uint32_t*)&h0, *(uint32_t*)&h1);
    } else {
        int b = (bid - WBLOCKS) * blockDim.x + threadIdx.x;
        int e = groups[b * GCOLS];
        int lane = threadIdx.x & 31;
        unsigned mask = __match_any_sync(0xffffffffu, e);
        int leader = __ffs(mask) - 1;
        int prefix = __popc(mask & ((1u << lane) - 1));
        int base = 0;
        if (lane == leader) base = atomicAdd(&g_fill[e], __popc(mask));
        base = __shfl_sync(0xffffffffu, base, leader);
        g_rowpad[e * B_ROWS + base + prefix] = b;
    }
}

// ---------------- persistent grouped GEMM: A fp32->fp16 in registers ----------------
__global__ __launch_bounds__(256, 2)
void gemm_mma(const float* __restrict__ x, const float* __restrict__ bias,
              float* __restrict__ out) {
    extern __shared__ char sm[];
    int* sm_w   = (int*)sm;
    int* s_cum  = (int*)(sm + 16);
    int* s_fill = (int*)(sm + 64);
    int* srows  = (int*)(sm + 256);
    const uint32_t smu = smem_u32(sm);

    const int tid  = threadIdx.x;
    const int lane = tid & 31;
    const int wid  = tid >> 5;

    if (tid < NE) s_fill[tid] = g_fill[tid];
    __syncthreads();
    if (tid == 0) {
        int c = 0;
        s_cum[0] = 0;
        for (int e = 0; e < NE; e++) {
            c += (s_fill[e] + TM - 1) / TM;
            s_cum[e + 1] = c;
        }
    }
    __syncthreads();
    const int nwork = s_cum[NE] * NCOLT;

    // warp compute coords: warp tile 32x64
    const int m0w = (wid >> 1) * 32;
    const int n0w = (wid & 1) * 64;
    const int g   = lane >> 2;              // A fragment row within 8
    const int t2  = (lane & 3) * 2;         // A fragment k-pair offset
    const int lr = (lane & 7) + ((lane >> 3) & 1) * 8;
    const int lc = (lane >> 4) * 8;
    const int b_lm_base = (lr * SB + n0w + lc) * 2;
    // A LDS base: row (m0w+g), k-col t2 (fp32)
    const uint32_t a_lds = smu + A32OF + (m0w + g) * SA32 + t2 * 4;

    // A32 cp.async: 8 chunks/thread/stage; chunk c: row c>>4, sector c&15 (16B)
    uint32_t a32sw[8];
#pragma unroll
    for (int t = 0; t < 8; t++) {
        int c = tid + t * 256;
        a32sw[t] = smu + A32OF + (c >> 4) * SA32 + (c & 15) * 16;
    }
    // B fp16 cp.async: 4 chunks/thread/stage
    int bk[4];
    uint32_t bso[4];
#pragma unroll
    for (int t = 0; t < 4; t++) {
        int c = tid + t * 256;
        bk[t] = c >> 4;
        bso[t] = smu + B16OF + bk[t] * (SB * 2) + (c & 15) * 16;
    }
    const int bsec = tid & 15;

    const int rl = lane >> 2;
    const int cl = (lane & 3) * 2;

    for (;;) {
        if (tid == 0) sm_w[0] = atomicAdd(&g_work, 1);
        __syncthreads();
        const int w = sm_w[0];
        if (w >= nwork) break;

        const int n0 = (w & (NCOLT - 1)) * TN;
        const int t  = w >> 2;
        int e = 0;
        while (t >= s_cum[e + 1]) e++;
        const int rowbase = (t - s_cum[e]) * TM;
        const int cnt  = s_fill[e];
        const int rows = (cnt - rowbase < TM) ? (cnt - rowbase) : TM;

        if (tid < TM) srows[tid] = (tid < rows) ? g_rowpad[e * B_ROWS + rowbase + tid] : -1;
        __syncthreads();

        const float* agp[8];
#pragma unroll
        for (int tt = 0; tt < 8; tt++) {
            int c = tid + tt * 256;
            int gr = srows[c >> 4]; if (gr < 0) gr = 0;
            agp[tt] = x + (size_t)gr * DIN + (c & 15) * 4;
        }
        const __half* bg[4];
#pragma unroll
        for (int tt = 0; tt < 4; tt++)
            bg[tt] = g_wh + ((size_t)e * DIN + bk[tt]) * DOUT + n0 + bsec * 8;

        float c[2][8][4];
#pragma unroll
        for (int mt = 0; mt < 2; mt++)
#pragma unroll
            for (int nt = 0; nt < 8; nt++)
#pragma unroll
                for (int j = 0; j < 4; j++) c[mt][nt][j] = 0.f;

        // prologue: fill stage 0 (A32 buf0, B buf0)
#pragma unroll
        for (int tt = 0; tt < 8; tt++) CP_ASYNC16(a32sw[tt], agp[tt]);
#pragma unroll
        for (int tt = 0; tt < 4; tt++) CP_ASYNC16(bso[tt], bg[tt]);
        CP_COMMIT();

        for (int kt = 0; kt < NSTAGE; kt++) {
            CP_WAIT0();
            __syncthreads();          // A32[kt&1], B[kt&1] ready for all warps

            // prefetch stage kt+1 into the other buffers (hidden under compute)
            if (kt + 1 < NSTAGE) {
                const uint32_t ao = ((kt + 1) & 1) * A32BUF;
                const uint32_t bo = ((kt + 1) & 1) * B16BUF;
                const int ka = (kt + 1) * TK;
                const size_t kb = (size_t)((kt + 1) * TK) * DOUT;
#pragma unroll
                for (int tt = 0; tt < 8; tt++) CP_ASYNC16(a32sw[tt] + ao, agp[tt] + ka);
#pragma unroll
                for (int tt = 0; tt < 4; tt++) CP_ASYNC16(bso[tt] + bo, bg[tt] + kb);
            }
            CP_COMMIT();

            const uint32_t ab = a_lds + (kt & 1) * A32BUF;
            const uint32_t bb = smu + B16OF + (kt & 1) * B16BUF;
#pragma unroll
            for (int ks = 0; ks < 4; ks++) {
                // A fragments: direct LDS.64 of fp32 pairs + cvt (replaces ldmatrix)
                uint32_t ah[2][4];
#pragma unroll
                for (int mt = 0; mt < 2; mt++) {
                    const uint32_t ao = ab + mt * (16 * SA32) + ks * 64;
                    ah[mt][0] = lds_cvt(ao);                    // (g,      t2)
                    ah[mt][1] = lds_cvt(ao + 8 * SA32);         // (g+8,    t2)
                    ah[mt][2] = lds_cvt(ao + 32);               // (g,      t2+8)
                    ah[mt][3] = lds_cvt(ao + 8 * SA32 + 32);    // (g+8,    t2+8)
                }
                uint32_t bh[4][4];
#pragma unroll
                for (int p = 0; p < 4; p++)
                    ldsm_x4_t(bh[p], bb + b_lm_base + (ks * 16 * SB + p * 16) * 2);
#pragma unroll
                for (int mt = 0; mt < 2; mt++)
#pragma unroll
                    for (int p = 0; p < 4; p++) {
                        mma_f16(c[mt][2 * p],     ah[mt], &bh[p][0]);
                        mma_f16(c[mt][2 * p + 1], ah[mt], &bh[p][2]);
                    }
            }
        }

        // epilogue: bias + scattered stores
#pragma unroll
        for (int mt = 0; mt < 2; mt++) {
            const int lm0 = m0w + mt * 16 + rl;
            const int r0 = srows[lm0];
            const int r1 = srows[lm0 + 8];
#pragma unroll
            for (int nt = 0; nt < 8; nt++) {
                const int gcol = n0 + n0w + nt * 8 + cl;
                const float2 bv2 = *(const float2*)(bias + e * DOUT + gcol);
                if (r0 >= 0) {
                    float2 v = make_float2(c[mt][nt][0] + bv2.x, c[mt][nt][1] + bv2.y);
                    *(float2*)(out + (size_t)r0 * DOUT + gcol) = v;
                }
                if (r1 >= 0) {
                    float2 v = make_float2(c[mt][nt][2] + bv2.x, c[mt][nt][3] + bv2.y);
                    *(float2*)(out + (size_t)r1 * DOUT + gcol) = v;
                }
            }
        }
        __syncthreads();   // srows stable until all warps finish epilogue
    }

    // self-reset for next replay
    __syncthreads();
    if (tid == 0) {
        int prev = atomicAdd(&g_done, 1);
        if (prev == GEMM_GRID - 1) {
#pragma unroll
            for (int i = 0; i < NE; i++) g_fill[i] = 0;
            g_work = 0;
            g_done = 0;
            __threadfence();
        }
    }
}

// ---------------- launch ----------------
extern "C" void kernel_launch(void* const* d_in, const int* in_sizes, int n_in,
                              void* d_out, int out_size) {
    const float* x      = (const float*)d_in[0];
    const int*   groups = (const int*)d_in[1];
    const float* W      = (const float*)d_in[2];
    const float* bias   = (const float*)d_in[3];
    float*       out    = (float*)d_out;

    cudaFuncSetAttribute(gemm_mma, cudaFuncAttributeMaxDynamicSharedMemorySize, GEMM_SMEM);

    prep_kernel<<<PREP_GRID, 256>>>(W, groups);
    gemm_mma<<<GEMM_GRID, 256, GEMM_SMEM>>>(x, bias, out);
}

// round 15
// speedup vs baseline: 1.0198x; 1.0198x over previous
#include <cuda_runtime.h>
#include <cuda_fp16.h>
#include <cstdint>

// ---------------- problem constants ----------------
#define B_ROWS 16384
#define DIN 512
#define DOUT 512
#define NE 8
#define GCOLS 2

// ---------------- GEMM tiling ----------------
#define TM 128
#define TN 128
#define TK 32
#define NSTAGE (DIN / TK)          // 16
#define NCOLT (DOUT / TN)          // 4

#define SA 40      // A16 smem row stride (halves): 80B
#define SB 136     // B smem row stride (halves): 272B

// smem layout (bytes)
#define A32OF 1024
#define A32BUF (TM * TK * 4)            // 16384 (linear, 128B rows), x2
#define A16OF (A32OF + 2 * A32BUF)      // 33792
#define A16BUF (TM * SA * 2)            // 10240, x2
#define B16OF (A16OF + 2 * A16BUF)      // 54272
#define B16BUF (TK * SB * 2)            // 8704, x3 RING (fixes R14 race)
#define GEMM_SMEM (B16OF + 3 * B16BUF)  // 80384 -> 2 CTAs/SM (161KB <= 228KB)

#define GEMM_GRID 304

// ---------------- device scratch ----------------
__device__ int g_fill[NE];
__device__ int g_work;
__device__ int g_done;
__device__ int g_rowpad[NE * B_ROWS];

__device__ __align__(16) __half g_wh[NE * DIN * DOUT];   // [e][k][n]

// ---------------- helpers ----------------
__device__ __forceinline__ uint32_t smem_u32(const void* p) {
    uint32_t a;
    asm("{ .reg .u64 t; cvta.to.shared.u64 t, %1; cvt.u32.u64 %0, t; }" : "=r"(a) : "l"(p));
    return a;
}
__device__ __forceinline__ void ldsm_x4(uint32_t* r, uint32_t addr) {
    asm volatile("ldmatrix.sync.aligned.m8n8.x4.shared.b16 {%0,%1,%2,%3}, [%4];"
                 : "=r"(r[0]), "=r"(r[1]), "=r"(r[2]), "=r"(r[3]) : "r"(addr));
}
__device__ __forceinline__ void ldsm_x4_t(uint32_t* r, uint32_t addr) {
    asm volatile("ldmatrix.sync.aligned.m8n8.x4.trans.shared.b16 {%0,%1,%2,%3}, [%4];"
                 : "=r"(r[0]), "=r"(r[1]), "=r"(r[2]), "=r"(r[3]) : "r"(addr));
}
__device__ __forceinline__ void mma_f16(float* c, const uint32_t* a, const uint32_t* b) {
    asm volatile(
        "mma.sync.aligned.m16n8k16.row.col.f32.f16.f16.f32 "
        "{%0,%1,%2,%3}, {%4,%5,%6,%7}, {%8,%9}, {%0,%1,%2,%3};"
        : "+f"(c[0]), "+f"(c[1]), "+f"(c[2]), "+f"(c[3])
        : "r"(a[0]), "r"(a[1]), "r"(a[2]), "r"(a[3]), "r"(b[0]), "r"(b[1]));
}
__device__ __forceinline__ void cvt_chunk(uint32_t src, uint32_t dst) {
    float x0, x1, x2, x3;
    asm volatile("ld.shared.v4.f32 {%0,%1,%2,%3}, [%4];"
                 : "=f"(x0), "=f"(x1), "=f"(x2), "=f"(x3) : "r"(src));
    uint32_t h0, h1;
    asm volatile("cvt.rn.f16x2.f32 %0, %1, %2;" : "=r"(h0) : "f"(x1), "f"(x0));
    asm volatile("cvt.rn.f16x2.f32 %0, %1, %2;" : "=r"(h1) : "f"(x3), "f"(x2));
    asm volatile("st.shared.v2.u32 [%0], {%1,%2};" :: "r"(dst), "r"(h0), "r"(h1) : "memory");
}
#define CP_ASYNC16(saddr, gaddr) \
    asm volatile("cp.async.cg.shared.global [%0], [%1], 16;" :: "r"(saddr), "l"(gaddr))
#define CP_COMMIT() asm volatile("cp.async.commit_group;")
#define CP_WAIT0()  asm volatile("cp.async.wait_group 0;" ::: "memory")

// ---------------- prep: cvt W, scatter ----------------
#define WBLOCKS (NE * DIN * DOUT / 4 / 256)
#define SBLOCKS (B_ROWS / 256)
#define PREP_GRID (WBLOCKS + SBLOCKS)

__global__ void prep_kernel(const float* __restrict__ W, const int* __restrict__ groups) {
    int bid = blockIdx.x;
    if (bid < WBLOCKS) {
        int i = bid * blockDim.x + threadIdx.x;
        float4 v = ((const float4*)W)[i];
        __half2 h0 = __floats2half2_rn(v.x, v.y);
        __half2 h1 = __floats2half2_rn(v.z, v.w);
        ((uint2*)g_wh)[i] = make_uint2(*(uint32_t*)&h0, *(uint32_t*)&h1);
    } else {
        int b = (bid - WBLOCKS) * blockDim.x + threadIdx.x;
        int e = groups[b * GCOLS];
        int lane = threadIdx.x & 31;
        unsigned mask = __match_any_sync(0xffffffffu, e);
        int leader = __ffs(mask) - 1;
        int prefix = __popc(mask & ((1u << lane) - 1));
        int base = 0;
        if (lane == leader) base = atomicAdd(&g_fill[e], __popc(mask));
        base = __shfl_sync(0xffffffffu, base, leader);
        g_rowpad[e * B_ROWS + base + prefix] = b;
    }
}

// ---------------- persistent grouped GEMM: convert pipelined, B 3-ring ----------------
__global__ __launch_bounds__(256, 2)
void gemm_mma(const float* __restrict__ x, const float* __restrict__ bias,
              float* __restrict__ out) {
    extern __shared__ char sm[];
    int* sm_w   = (int*)sm;
    int* s_cum  = (int*)(sm + 16);
    int* s_fill = (int*)(sm + 64);
    int* srows  = (int*)(sm + 256);
    const uint32_t smu = smem_u32(sm);

    const int tid  = threadIdx.x;
    const int lane = tid & 31;
    const int wid  = tid >> 5;

    if (tid < NE) s_fill[tid] = g_fill[tid];
    __syncthreads();
    if (tid == 0) {
        int c = 0;
        s_cum[0] = 0;
        for (int e = 0; e < NE; e++) {
            c += (s_fill[e] + TM - 1) / TM;
            s_cum[e + 1] = c;
        }
    }
    __syncthreads();
    const int nwork = s_cum[NE] * NCOLT;

    const int m0w = (wid >> 1) * 32;
    const int n0w = (wid & 1) * 64;
    const int lr = (lane & 7) + ((lane >> 3) & 1) * 8;
    const int lc = (lane >> 4) * 8;
    const int a_lm_base = ((m0w + lr) * SA + lc) * 2;
    const int b_lm_base = (lr * SB + n0w + lc) * 2;

    uint32_t a32s[4], a16d[4];
#pragma unroll
    for (int t = 0; t < 4; t++) {
        int c = tid + t * 256;
        int row = c >> 3, sec = c & 7;
        a32s[t] = smu + A32OF + row * 128 + sec * 16;
        a16d[t] = smu + A16OF + row * (SA * 2) + sec * 8;
    }
    int bk[2];
    uint32_t bso[2];
#pragma unroll
    for (int t = 0; t < 2; t++) {
        int c = tid + t * 256;
        bk[t] = c >> 4;
        bso[t] = smu + B16OF + bk[t] * (SB * 2) + (c & 15) * 16;
    }
    const int bsec = tid & 15;

    const int rl = lane >> 2;
    const int cl = (lane & 3) * 2;

    for (;;) {
        if (tid == 0) sm_w[0] = atomicAdd(&g_work, 1);
        __syncthreads();
        const int w = sm_w[0];
        if (w >= nwork) break;

        const int n0 = (w & (NCOLT - 1)) * TN;
        const int t  = w >> 2;
        int e = 0;
        while (t >= s_cum[e + 1]) e++;
        const int rowbase = (t - s_cum[e]) * TM;
        const int cnt  = s_fill[e];
        const int rows = (cnt - rowbase < TM) ? (cnt - rowbase) : TM;

        if (tid < TM) srows[tid] = (tid < rows) ? g_rowpad[e * B_ROWS + rowbase + tid] : -1;
        __syncthreads();

        const float* agp[4];
#pragma unroll
        for (int tt = 0; tt < 4; tt++) {
            int c = tid + tt * 256;
            int gr = srows[c >> 3]; if (gr < 0) gr = 0;
            agp[tt] = x + (size_t)gr * DIN + (c & 7) * 4;
        }
        const __half* bg[2];
#pragma unroll
        for (int tt = 0; tt < 2; tt++)
            bg[tt] = g_wh + ((size_t)e * DIN + bk[tt]) * DOUT + n0 + bsec * 8;

        float c[2][8][4];
#pragma unroll
        for (int mt = 0; mt < 2; mt++)
#pragma unroll
            for (int nt = 0; nt < 8; nt++)
#pragma unroll
                for (int j = 0; j < 4; j++) c[mt][nt][j] = 0.f;

        // prologue: A32(0)+B(0)->slot0; wait; convert(0); A32(1)+B(1)->slot1
#pragma unroll
        for (int tt = 0; tt < 4; tt++) CP_ASYNC16(a32s[tt], agp[tt]);
#pragma unroll
        for (int tt = 0; tt < 2; tt++) CP_ASYNC16(bso[tt], bg[tt]);
        CP_COMMIT();
        CP_WAIT0();
        __syncthreads();
#pragma unroll
        for (int tt = 0; tt < 4; tt++) cvt_chunk(a32s[tt], a16d[tt]);
#pragma unroll
        for (int tt = 0; tt < 4; tt++) CP_ASYNC16(a32s[tt] + A32BUF, agp[tt] + TK);
#pragma unroll
        for (int tt = 0; tt < 2; tt++) CP_ASYNC16(bso[tt] + B16BUF, bg[tt] + (size_t)TK * DOUT);
        CP_COMMIT();

        // B ring slots: MMA(kt) reads kt%3; fill targets (kt+2)%3
        int brd = 0;        // kt % 3
        int bfl = 2;        // (kt+2) % 3
        for (int kt = 0; kt < NSTAGE; kt++) {
            CP_WAIT0();
            __syncthreads();   // A32(kt+1)/B(kt+1) arrived; convert(kt) visible

            // fill stage kt+2: A32 -> A32[kt&1] (its reader convert(kt) completed
            // before the sync), B -> ring slot (kt+2)%3 (distinct from kt%3 and (kt+1)%3)
            if (kt + 2 < NSTAGE) {
                const uint32_t ao = (kt & 1) * A32BUF;
                const uint32_t bo = bfl * B16BUF;
                const int ka = (kt + 2) * TK;
                const size_t kb = (size_t)((kt + 2) * TK) * DOUT;
#pragma unroll
                for (int tt = 0; tt < 4; tt++) CP_ASYNC16(a32s[tt] + ao, agp[tt] + ka);
#pragma unroll
                for (int tt = 0; tt < 2; tt++) CP_ASYNC16(bso[tt] + bo, bg[tt] + kb);
            }
            CP_COMMIT();

            // convert(kt+1) — interleaves with MMA(kt) (no barrier between;
            // writes A16[(kt+1)&1], whose last reader MMA(kt-1) pre-dates the sync)
            if (kt + 1 < NSTAGE) {
                const uint32_t off32 = ((kt + 1) & 1) * A32BUF;
                const uint32_t off16 = ((kt + 1) & 1) * A16BUF;
#pragma unroll
                for (int tt = 0; tt < 4; tt++) cvt_chunk(a32s[tt] + off32, a16d[tt] + off16);
            }

            // MMA(kt)
            const uint32_t ab = smu + A16OF + (kt & 1) * A16BUF;
            const uint32_t bb = smu + B16OF + brd * B16BUF;
#pragma unroll
            for (int ks = 0; ks < 2; ks++) {
                const int kso = ks * 16;
                uint32_t ah[2][4];
#pragma unroll
                for (int mt = 0; mt < 2; mt++)
                    ldsm_x4(ah[mt], ab + a_lm_base + (mt * 16 * SA + kso) * 2);
                uint32_t bh[4][4];
#pragma unroll
                for (int p = 0; p < 4; p++)
                    ldsm_x4_t(bh[p], bb + b_lm_base + (kso * SB + p * 16) * 2);
#pragma unroll
                for (int mt = 0; mt < 2; mt++)
#pragma unroll
                    for (int p = 0; p < 4; p++) {
                        mma_f16(c[mt][2 * p],     ah[mt], &bh[p][0]);
                        mma_f16(c[mt][2 * p + 1], ah[mt], &bh[p][2]);
                    }
            }

            brd = (brd + 1 == 3) ? 0 : brd + 1;
            bfl = (bfl + 1 == 3) ? 0 : bfl + 1;
        }

        // epilogue
#pragma unroll
        for (int mt = 0; mt < 2; mt++) {
            const int lm0 = m0w + mt * 16 + rl;
            const int r0 = srows[lm0];
            const int r1 = srows[lm0 + 8];
#pragma unroll
            for (int nt = 0; nt < 8; nt++) {
                const int gcol = n0 + n0w + nt * 8 + cl;
                const float2 bv2 = *(const float2*)(bias + e * DOUT + gcol);
                if (r0 >= 0) {
                    float2 v = make_float2(c[mt][nt][0] + bv2.x, c[mt][nt][1] + bv2.y);
                    *(float2*)(out + (size_t)r0 * DOUT + gcol) = v;
                }
                if (r1 >= 0) {
                    float2 v = make_float2(c[mt][nt][2] + bv2.x, c[mt][nt][3] + bv2.y);
                    *(float2*)(out + (size_t)r1 * DOUT + gcol) = v;
                }
            }
        }
        __syncthreads();
    }

    __syncthreads();
    if (tid == 0) {
        int prev = atomicAdd(&g_done, 1);
        if (prev == GEMM_GRID - 1) {
#pragma unroll
            for (int i = 0; i < NE; i++) g_fill[i] = 0;
            g_work = 0;
            g_done = 0;
            __threadfence();
        }
    }
}

// ---------------- launch ----------------
extern "C" void kernel_launch(void* const* d_in, const int* in_sizes, int n_in,
                              void* d_out, int out_size) {
    const float* x      = (const float*)d_in[0];
    const int*   groups = (const int*)d_in[1];
    const float* W      = (const float*)d_in[2];
    const float* bias   = (const float*)d_in[3];
    float*       out    = (float*)d_out;

    cudaFuncSetAttribute(gemm_mma, cudaFuncAttributeMaxDynamicSharedMemorySize, GEMM_SMEM);

    prep_kernel<<<PREP_GRID, 256>>>(W, groups);
    gemm_mma<<<GEMM_GRID, 256, GEMM_SMEM>>>(x, bias, out);
}